// round 1
// baseline (speedup 1.0000x reference)
#include <cuda_runtime.h>
#include <stdint.h>

#define IW 1024
#define IH 1024
#define NIMG 8
#define PLANE (IW*IH)
#define NP (NIMG*PLANE)

// ---- scratch (static device globals; no allocation allowed) ----
__device__ float g_hb[NP];            // horizontal-blurred gray
__device__ float g_bl[NP];            // fully blurred
__device__ float g_mag[NP];           // gradient magnitude
__device__ unsigned char g_dir[NP];   // quantized gradient dir (0..7)
__device__ unsigned char g_code[NP];  // 0=off, 1=weak, 2=strong
__device__ int           g_lab[NP];   // union-find labels
__device__ unsigned char g_flag[NP];  // root-has-strong flags

// Gaussian(ksize=5, sigma=1) normalized weights (f32-rounded)
__device__ __constant__ float GW[5] = {
    0.0544886855f, 0.2442013420f, 0.4026199447f, 0.2442013420f, 0.0544886855f };

__device__ __constant__ int NDY[8] = {0,-1,-1,-1, 0, 1, 1, 1};
__device__ __constant__ int NDX[8] = {1, 1, 0,-1,-1,-1, 0, 1};

// ---------------------------------------------------------------
// 1. gray conversion fused with horizontal Gaussian (reflect pad)
__global__ void k_gray_hblur(const float* __restrict__ img) {
    int idx = blockIdx.x * blockDim.x + threadIdx.x;
    if (idx >= NP) return;
    int n = idx >> 20;
    int rem = idx & (PLANE - 1);
    int y = rem >> 10;
    int x = rem & (IW - 1);
    const float* rch = img + (size_t)n * 3 * PLANE;
    const float* gch = rch + PLANE;
    const float* bch = gch + PLANE;
    int rowoff = y << 10;
    float acc = 0.f;
#pragma unroll
    for (int k = 0; k < 5; k++) {
        int xx = x + k - 2;
        xx = (xx < 0) ? -xx : ((xx >= IW) ? (2 * IW - 2 - xx) : xx);
        int o = rowoff + xx;
        float gr = 0.299f * rch[o] + 0.587f * gch[o] + 0.114f * bch[o];
        acc = fmaf(GW[k], gr, acc);
    }
    g_hb[idx] = acc;
}

// 2. vertical Gaussian (reflect pad)
__global__ void k_vblur() {
    int idx = blockIdx.x * blockDim.x + threadIdx.x;
    if (idx >= NP) return;
    int rem = idx & (PLANE - 1);
    int y = rem >> 10;
    int x = rem & (IW - 1);
    int base = idx - rem;  // n*PLANE
    float acc = 0.f;
#pragma unroll
    for (int k = 0; k < 5; k++) {
        int yy = y + k - 2;
        yy = (yy < 0) ? -yy : ((yy >= IH) ? (2 * IH - 2 - yy) : yy);
        acc = fmaf(GW[k], g_hb[base + (yy << 10) + x], acc);
    }
    g_bl[idx] = acc;
}

// 3. Sobel + magnitude + quantized direction (edge/clamp pad)
__global__ void k_sobel() {
    int idx = blockIdx.x * blockDim.x + threadIdx.x;
    if (idx >= NP) return;
    int rem = idx & (PLANE - 1);
    int y = rem >> 10;
    int x = rem & (IW - 1);
    const float* p = g_bl + (idx - rem);
    int ym = (y > 0) ? y - 1 : 0;
    int yp = (y < IH - 1) ? y + 1 : IH - 1;
    int xm = (x > 0) ? x - 1 : 0;
    int xp = (x < IW - 1) ? x + 1 : IW - 1;
    float a = p[(ym << 10) + xm], b = p[(ym << 10) + x], c = p[(ym << 10) + xp];
    float d = p[(y  << 10) + xm],                         e = p[(y  << 10) + xp];
    float f = p[(yp << 10) + xm], g = p[(yp << 10) + x], h = p[(yp << 10) + xp];
    float gx = (c - a) + 2.f * (e - d) + (h - f);
    float gy = (f - a) + 2.f * (g - b) + (h - c);
    float m = sqrtf(gx * gx + gy * gy + 1e-6f);
    // replicate: round((180/pi * atan2) / 45), round-half-even
    float deg = atan2f(gy, gx) * 57.29577951308232f;
    float t = rintf(deg / 45.0f);           // in [-4, 4]
    int it = (int)t;
    g_dir[idx] = (unsigned char)((it + 8) & 7);
    g_mag[idx] = m;
}

// 4. NMS (zero pad for neighbors) + write masked magnitude + threshold code
__global__ void k_nms(float* __restrict__ out_mag) {
    int idx = blockIdx.x * blockDim.x + threadIdx.x;
    if (idx >= NP) return;
    int rem = idx & (PLANE - 1);
    int y = rem >> 10;
    int x = rem & (IW - 1);
    int base = idx - rem;
    float m = g_mag[idx];
    int d  = g_dir[idx];
    int d2 = (d + 4) & 7;
    int y1 = y + NDY[d],  x1 = x + NDX[d];
    int y2 = y + NDY[d2], x2 = x + NDX[d2];
    float mp = (y1 >= 0 && y1 < IH && x1 >= 0 && x1 < IW) ? g_mag[base + (y1 << 10) + x1] : 0.f;
    float mn = (y2 >= 0 && y2 < IH && x2 >= 0 && x2 < IW) ? g_mag[base + (y2 << 10) + x2] : 0.f;
    bool keep = ((m - mp) > 0.f) && ((m - mn) > 0.f);
    float mo = keep ? m : 0.f;
    out_mag[idx] = mo;
    g_code[idx] = (unsigned char)((mo > 0.1f ? 1 : 0) + (mo > 0.2f ? 1 : 0));
}

// ---------------------------------------------------------------
// hysteresis as connected-component labeling (union-find, min-hooking)
__device__ __forceinline__ int uf_rep(int x) {
    volatile int* L = g_lab;
    int r = L[x];
    int p = L[r];
    while (p != r) { r = p; p = L[r]; }
    return r;
}

__device__ __forceinline__ void uf_unite(int a, int b) {
    int ra = uf_rep(a), rb = uf_rep(b);
    while (ra != rb) {
        if (ra < rb) { int t = ra; ra = rb; rb = t; }
        int old = atomicMin(&g_lab[ra], rb);
        if (old == ra) break;
        ra = uf_rep(old);
        rb = uf_rep(rb);
    }
}

// 5. init labels + zero flags
__global__ void k_ccl_init() {
    int idx = blockIdx.x * blockDim.x + threadIdx.x;
    if (idx >= NP) return;
    g_flag[idx] = 0;
    g_lab[idx] = g_code[idx] ? idx : -1;
}

// 6. merge forward 8-neighbors (within image plane; planes never touch)
__global__ void k_ccl_merge() {
    int idx = blockIdx.x * blockDim.x + threadIdx.x;
    if (idx >= NP) return;
    if (!g_code[idx]) return;
    int rem = idx & (PLANE - 1);
    int y = rem >> 10;
    int x = rem & (IW - 1);
    if (x + 1 < IW && g_code[idx + 1]) uf_unite(idx, idx + 1);
    if (y + 1 < IH) {
        if (x > 0      && g_code[idx + IW - 1]) uf_unite(idx, idx + IW - 1);
        if (              g_code[idx + IW    ]) uf_unite(idx, idx + IW);
        if (x + 1 < IW && g_code[idx + IW + 1]) uf_unite(idx, idx + IW + 1);
    }
}

// 7. flatten + mark strong roots
__global__ void k_ccl_flatten() {
    int idx = blockIdx.x * blockDim.x + threadIdx.x;
    if (idx >= NP) return;
    unsigned char c = g_code[idx];
    if (!c) return;
    int r = uf_rep(idx);
    g_lab[idx] = r;
    if (c == 2) g_flag[r] = 1;
}

// 8. final hysteresis output
__global__ void k_final(float* __restrict__ out_hyst) {
    int idx = blockIdx.x * blockDim.x + threadIdx.x;
    if (idx >= NP) return;
    float v = 0.f;
    if (g_code[idx] && g_flag[g_lab[idx]]) v = 1.f;
    out_hyst[idx] = v;
}

// ---------------------------------------------------------------
extern "C" void kernel_launch(void* const* d_in, const int* in_sizes, int n_in,
                              void* d_out, int out_size) {
    const float* img = (const float*)d_in[0];
    float* out = (float*)d_out;           // [0,NP): magnitude, [NP,2NP): hysteresis

    const int T = 256;
    const int B = (NP + T - 1) / T;

    k_gray_hblur<<<B, T>>>(img);
    k_vblur<<<B, T>>>();
    k_sobel<<<B, T>>>();
    k_nms<<<B, T>>>(out);
    k_ccl_init<<<B, T>>>();
    k_ccl_merge<<<B, T>>>();
    k_ccl_flatten<<<B, T>>>();
    k_final<<<B, T>>>(out + NP);
}

// round 2
// speedup vs baseline: 1.1887x; 1.1887x over previous
#include <cuda_runtime.h>
#include <stdint.h>

#define IW 1024
#define IH 1024
#define NIMG 8
#define PLANE (IW*IH)
#define NP (NIMG*PLANE)

// ---- persistent scratch ----
__device__ unsigned char g_code[NP];  // 0=off, 1=weak, 2=strong
__device__ int           g_lab[NP];   // union-find labels
__device__ unsigned char g_flag[NP];  // root-has-strong flags

// Gaussian(5, sigma=1) weights — MUST stay identical to round-1 values
__device__ __constant__ float GW[5] = {
    0.0544886855f, 0.2442013420f, 0.4026199447f, 0.2442013420f, 0.0544886855f };

__device__ __constant__ int NDY[8] = {0,-1,-1,-1, 0, 1, 1, 1};
__device__ __constant__ int NDX[8] = {1, 1, 0,-1,-1,-1, 0, 1};

// =================================================================
// Fused front: gray -> hblur -> vblur -> sobel/mag/dir -> NMS ->
// thresholds -> write out_mag, g_code, g_lab(init), g_flag(zero)
//
// Tile 32x32, halos: gray 4, hblur (y:4,x:2), blurred 2, mag 1.
// smem: A holds gray(40x40) then blurred(36x36); B holds hblur(40x36)
// then mag(34x34).
// =================================================================
__global__ __launch_bounds__(256) void k_front(const float* __restrict__ img,
                                               float* __restrict__ out_mag) {
    __shared__ float A[40*40];
    __shared__ float B[40*36];
    __shared__ unsigned char DIR[32*32];

    const int tid = threadIdx.x;
    const int x0 = blockIdx.x * 32;
    const int y0 = blockIdx.y * 32;
    const int n  = blockIdx.z;
    const float* rch = img + (size_t)n * 3 * PLANE;
    const float* gch = rch + PLANE;
    const float* bch = gch + PLANE;

    // ---- stage 1: gray (40x40), reflect pad ----
    for (int i = tid; i < 40*40; i += 256) {
        int ly = i / 40, lx = i - ly*40;
        int gy = y0 + ly - 4;
        int gx = x0 + lx - 4;
        gy = (gy < 0) ? -gy : ((gy >= IH) ? 2*IH - 2 - gy : gy);
        gx = (gx < 0) ? -gx : ((gx >= IW) ? 2*IW - 2 - gx : gx);
        int o = (gy << 10) + gx;
        A[i] = 0.299f * rch[o] + 0.587f * gch[o] + 0.114f * bch[o];
    }
    __syncthreads();

    // ---- stage 2: horizontal blur (40 rows x 36 cols) ----
    for (int i = tid; i < 40*36; i += 256) {
        int ly = i / 36, hx = i - ly*36;
        float acc = 0.f;
#pragma unroll
        for (int k = 0; k < 5; k++)
            acc = fmaf(GW[k], A[ly*40 + hx + k], acc);
        B[i] = acc;
    }
    __syncthreads();

    // ---- stage 3: vertical blur (36x36) into A ----
    for (int i = tid; i < 36*36; i += 256) {
        int by = i / 36, bx = i - by*36;
        float acc = 0.f;
#pragma unroll
        for (int k = 0; k < 5; k++)
            acc = fmaf(GW[k], B[(by + k)*36 + bx], acc);
        A[i] = acc;
    }
    __syncthreads();

    // ---- stage 4: sobel + magnitude (34x34) into B, dir (32x32) ----
    // blurred local index for global G: G - (y0-2)  /  G - (x0-2)
    for (int i = tid; i < 34*34; i += 256) {
        int my = i / 34, mx = i - my*34;
        int gy = y0 + my - 1;
        int gx = x0 + mx - 1;
        float m = 0.f;
        if (gy >= 0 && gy < IH && gx >= 0 && gx < IW) {
            int ym = (gy > 0)    ? gy - 1 : 0;
            int yp = (gy < IH-1) ? gy + 1 : IH - 1;
            int xm = (gx > 0)    ? gx - 1 : 0;
            int xp = (gx < IW-1) ? gx + 1 : IW - 1;
            int lym = ym - y0 + 2, lyc = gy - y0 + 2, lyp = yp - y0 + 2;
            int lxm = xm - x0 + 2, lxc = gx - x0 + 2, lxp = xp - x0 + 2;
            float a = A[lym*36+lxm], b = A[lym*36+lxc], c = A[lym*36+lxp];
            float d = A[lyc*36+lxm],                     e = A[lyc*36+lxp];
            float f = A[lyp*36+lxm], g = A[lyp*36+lxc], h = A[lyp*36+lxp];
            float gxv = (c - a) + 2.f * (e - d) + (h - f);
            float gyv = (f - a) + 2.f * (g - b) + (h - c);
            m = sqrtf(gxv * gxv + gyv * gyv + 1e-6f);
            if (my >= 1 && my <= 32 && mx >= 1 && mx <= 32) {
                float deg = atan2f(gyv, gxv) * 57.29577951308232f;
                int it = (int)rintf(deg / 45.0f);
                DIR[(my-1)*32 + (mx-1)] = (unsigned char)((it + 8) & 7);
            }
        }
        B[i] = m;
    }
    __syncthreads();

    // ---- stage 5: NMS + thresholds + CCL init ----
    for (int i = tid; i < 32*32; i += 256) {
        int cy = i / 32, cx = i - cy*32;
        int my = cy + 1, mx = cx + 1;
        float m = B[my*34 + mx];
        int d  = DIR[i];
        int d2 = (d + 4) & 7;
        float mp = B[(my + NDY[d ])*34 + (mx + NDX[d ])];
        float mn = B[(my + NDY[d2])*34 + (mx + NDX[d2])];
        bool keep = ((m - mp) > 0.f) && ((m - mn) > 0.f);
        float mo = keep ? m : 0.f;
        int gy = y0 + cy, gx = x0 + cx;
        int idx = n * PLANE + (gy << 10) + gx;
        unsigned char code = (unsigned char)((mo > 0.1f ? 1 : 0) + (mo > 0.2f ? 1 : 0));
        out_mag[idx] = mo;
        g_code[idx]  = code;
        g_lab[idx]   = code ? idx : -1;
        g_flag[idx]  = 0;
    }
}

// =================================================================
// hysteresis as connected-component labeling (union-find, min-hooking)
// =================================================================
__device__ __forceinline__ int uf_rep(int x) {
    volatile int* L = g_lab;
    int r = L[x];
    int p = L[r];
    while (p != r) { r = p; p = L[r]; }
    return r;
}

__device__ __forceinline__ void uf_unite(int a, int b) {
    int ra = uf_rep(a), rb = uf_rep(b);
    while (ra != rb) {
        if (ra < rb) { int t = ra; ra = rb; rb = t; }
        int old = atomicMin(&g_lab[ra], rb);
        if (old == ra) break;
        ra = uf_rep(old);
        rb = uf_rep(rb);
    }
}

__global__ __launch_bounds__(256) void k_ccl_merge() {
    int idx = blockIdx.x * blockDim.x + threadIdx.x;
    if (idx >= NP) return;
    if (!g_code[idx]) return;
    int rem = idx & (PLANE - 1);
    int y = rem >> 10;
    int x = rem & (IW - 1);
    if (x + 1 < IW && g_code[idx + 1]) uf_unite(idx, idx + 1);
    if (y + 1 < IH) {
        if (x > 0      && g_code[idx + IW - 1]) uf_unite(idx, idx + IW - 1);
        if (              g_code[idx + IW    ]) uf_unite(idx, idx + IW);
        if (x + 1 < IW && g_code[idx + IW + 1]) uf_unite(idx, idx + IW + 1);
    }
}

__global__ __launch_bounds__(256) void k_ccl_flatten() {
    int idx = blockIdx.x * blockDim.x + threadIdx.x;
    if (idx >= NP) return;
    unsigned char c = g_code[idx];
    if (!c) return;
    int r = uf_rep(idx);
    g_lab[idx] = r;
    if (c == 2) g_flag[r] = 1;
}

__global__ __launch_bounds__(256) void k_final(float* __restrict__ out_hyst) {
    int idx = blockIdx.x * blockDim.x + threadIdx.x;
    if (idx >= NP) return;
    float v = 0.f;
    if (g_code[idx] && g_flag[g_lab[idx]]) v = 1.f;
    out_hyst[idx] = v;
}

// =================================================================
extern "C" void kernel_launch(void* const* d_in, const int* in_sizes, int n_in,
                              void* d_out, int out_size) {
    const float* img = (const float*)d_in[0];
    float* out = (float*)d_out;   // [0,NP): magnitude, [NP,2NP): hysteresis

    dim3 fgrid(IW/32, IH/32, NIMG);
    k_front<<<fgrid, 256>>>(img, out);

    const int T = 256;
    const int B = (NP + T - 1) / T;
    k_ccl_merge<<<B, T>>>();
    k_ccl_flatten<<<B, T>>>();
    k_final<<<B, T>>>(out + NP);
}

// round 3
// speedup vs baseline: 1.8110x; 1.5234x over previous
#include <cuda_runtime.h>
#include <stdint.h>

#define IW 1024
#define IH 1024
#define NIMG 8
#define PLANE (IW*IH)
#define NP (NIMG*PLANE)

// ---- persistent scratch ----
__device__ unsigned char g_code[NP];  // 0=off, 1=weak, 2=strong
__device__ int           g_lab[NP];   // union-find labels (valid only where code!=0)
__device__ unsigned char g_flag[NP];  // root-has-strong flags (valid only where code!=0)

// Gaussian(5, sigma=1) weights — identical to passing version
__device__ __constant__ float GW[5] = {
    0.0544886855f, 0.2442013420f, 0.4026199447f, 0.2442013420f, 0.0544886855f };

__device__ __constant__ int NDY[8] = {0,-1,-1,-1, 0, 1, 1, 1};
__device__ __constant__ int NDX[8] = {1, 1, 0,-1,-1,-1, 0, 1};

// ---------- shared-memory union-find (tile-local) ----------
__device__ __forceinline__ int rep_s(volatile int* L, int x) {
    int r = L[x];
    int p = L[r];
    while (p != r) { r = p; p = L[r]; }
    return r;
}
__device__ __forceinline__ void unite_s(int* L, int a, int b) {
    volatile int* Lv = L;
    int ra = rep_s(Lv, a), rb = rep_s(Lv, b);
    while (ra != rb) {
        if (ra < rb) { int t = ra; ra = rb; rb = t; }
        int old = atomicMin(&L[ra], rb);
        if (old == ra) break;
        ra = rep_s(Lv, old);
        rb = rep_s(Lv, rb);
    }
}

// ---------- global union-find ----------
__device__ __forceinline__ int uf_rep(int x) {
    volatile int* L = g_lab;
    int r = L[x];
    int p = L[r];
    while (p != r) { r = p; p = L[r]; }
    return r;
}
__device__ __forceinline__ void uf_unite(int a, int b) {
    int ra = uf_rep(a), rb = uf_rep(b);
    while (ra != rb) {
        if (ra < rb) { int t = ra; ra = rb; rb = t; }
        int old = atomicMin(&g_lab[ra], rb);
        if (old == ra) break;
        ra = uf_rep(old);
        rb = uf_rep(rb);
    }
}

// =================================================================
// Fused front: gray -> hblur -> vblur -> sobel/mag/dir -> NMS ->
// thresholds -> tile-local CCL -> write out_mag, g_code, g_lab, g_flag
// =================================================================
__global__ __launch_bounds__(256) void k_front(const float* __restrict__ img,
                                               float* __restrict__ out_mag) {
    __shared__ float A[40*40];
    __shared__ float B[40*36];
    __shared__ unsigned char DIR[32*32];
    __shared__ unsigned char C[32*32];
    __shared__ int L[32*32];

    const int tid = threadIdx.x;
    const int x0 = blockIdx.x * 32;
    const int y0 = blockIdx.y * 32;
    const int n  = blockIdx.z;
    const float* rch = img + (size_t)n * 3 * PLANE;
    const float* gch = rch + PLANE;
    const float* bch = gch + PLANE;

    // ---- stage 1: gray (40x40), reflect pad ----
    for (int i = tid; i < 40*40; i += 256) {
        int ly = i / 40, lx = i - ly*40;
        int gy = y0 + ly - 4;
        int gx = x0 + lx - 4;
        gy = (gy < 0) ? -gy : ((gy >= IH) ? 2*IH - 2 - gy : gy);
        gx = (gx < 0) ? -gx : ((gx >= IW) ? 2*IW - 2 - gx : gx);
        int o = (gy << 10) + gx;
        A[i] = 0.299f * rch[o] + 0.587f * gch[o] + 0.114f * bch[o];
    }
    __syncthreads();

    // ---- stage 2: horizontal blur (40 x 36) ----
    for (int i = tid; i < 40*36; i += 256) {
        int ly = i / 36, hx = i - ly*36;
        float acc = 0.f;
#pragma unroll
        for (int k = 0; k < 5; k++)
            acc = fmaf(GW[k], A[ly*40 + hx + k], acc);
        B[i] = acc;
    }
    __syncthreads();

    // ---- stage 3: vertical blur (36x36) into A ----
    for (int i = tid; i < 36*36; i += 256) {
        int by = i / 36, bx = i - by*36;
        float acc = 0.f;
#pragma unroll
        for (int k = 0; k < 5; k++)
            acc = fmaf(GW[k], B[(by + k)*36 + bx], acc);
        A[i] = acc;
    }
    __syncthreads();

    // ---- stage 4: sobel + magnitude (34x34) into B, dir (32x32) ----
    for (int i = tid; i < 34*34; i += 256) {
        int my = i / 34, mx = i - my*34;
        int gy = y0 + my - 1;
        int gx = x0 + mx - 1;
        float m = 0.f;
        if (gy >= 0 && gy < IH && gx >= 0 && gx < IW) {
            int ym = (gy > 0)    ? gy - 1 : 0;
            int yp = (gy < IH-1) ? gy + 1 : IH - 1;
            int xm = (gx > 0)    ? gx - 1 : 0;
            int xp = (gx < IW-1) ? gx + 1 : IW - 1;
            int lym = ym - y0 + 2, lyc = gy - y0 + 2, lyp = yp - y0 + 2;
            int lxm = xm - x0 + 2, lxc = gx - x0 + 2, lxp = xp - x0 + 2;
            float a = A[lym*36+lxm], b = A[lym*36+lxc], c = A[lym*36+lxp];
            float d = A[lyc*36+lxm],                     e = A[lyc*36+lxp];
            float f = A[lyp*36+lxm], g = A[lyp*36+lxc], h = A[lyp*36+lxp];
            float gxv = (c - a) + 2.f * (e - d) + (h - f);
            float gyv = (f - a) + 2.f * (g - b) + (h - c);
            m = sqrtf(gxv * gxv + gyv * gyv + 1e-6f);
            if (my >= 1 && my <= 32 && mx >= 1 && mx <= 32) {
                float deg = atan2f(gyv, gxv) * 57.29577951308232f;
                int it = (int)rintf(deg / 45.0f);
                DIR[(my-1)*32 + (mx-1)] = (unsigned char)((it + 8) & 7);
            }
        }
        B[i] = m;
    }
    __syncthreads();

    // ---- stage 5: NMS + thresholds; seed local CCL ----
    for (int i = tid; i < 32*32; i += 256) {
        int cy = i >> 5, cx = i & 31;
        int my = cy + 1, mx = cx + 1;
        float m = B[my*34 + mx];
        int d  = DIR[i];
        int d2 = (d + 4) & 7;
        float mp = B[(my + NDY[d ])*34 + (mx + NDX[d ])];
        float mn = B[(my + NDY[d2])*34 + (mx + NDX[d2])];
        bool keep = ((m - mp) > 0.f) && ((m - mn) > 0.f);
        float mo = keep ? m : 0.f;
        unsigned char code = (unsigned char)((mo > 0.1f ? 1 : 0) + (mo > 0.2f ? 1 : 0));
        int gy = y0 + cy, gx = x0 + cx;
        int idx = n * PLANE + (gy << 10) + gx;
        out_mag[idx] = mo;
        g_code[idx]  = code;
        C[i] = code;
        L[i] = i;
    }
    __syncthreads();

    // ---- stage 6: tile-local union-find hooking ----
    for (int i = tid; i < 32*32; i += 256) {
        if (!C[i]) continue;
        int cx = i & 31, cy = i >> 5;
        if (cx < 31 && C[i + 1])  unite_s(L, i, i + 1);
        if (cy < 31) {
            if (cx > 0  && C[i + 31]) unite_s(L, i, i + 31);
            if (           C[i + 32]) unite_s(L, i, i + 32);
            if (cx < 31 && C[i + 33]) unite_s(L, i, i + 33);
        }
    }
    __syncthreads();

    // ---- stage 7: resolve tile roots, write global labels ----
    for (int i = tid; i < 32*32; i += 256) {
        if (!C[i]) continue;
        int r = i, p = L[r];
        while (p != r) { r = p; p = L[r]; }
        int gy = y0 + (i >> 5), gx = x0 + (i & 31);
        int idx = n * PLANE + (gy << 10) + gx;
        int ry = y0 + (r >> 5), rx = x0 + (r & 31);
        g_lab[idx]  = n * PLANE + (ry << 10) + rx;
        g_flag[idx] = 0;
    }
}

// =================================================================
// Boundary merge: only pixels on tile edges (16x fewer threads)
// =================================================================
#define PER_IMG (31*1024*2)
__global__ __launch_bounds__(256) void k_boundary() {
    int t = blockIdx.x * blockDim.x + threadIdx.x;
    if (t >= NIMG * PER_IMG) return;
    int n = t / PER_IMG;
    int r = t - n * PER_IMG;
    int base = n * PLANE;
    if (r < 31*1024) {
        // horizontal boundary: row y = 32b+31 vs y+1
        int b = r >> 10, x = r & 1023;
        int y = 32*b + 31;
        int i = base + (y << 10) + x;
        if (!g_code[i]) return;
        int j = i + IW;
        if (x > 0    && g_code[j - 1]) uf_unite(i, j - 1);
        if (            g_code[j    ]) uf_unite(i, j);
        if (x < 1023 && g_code[j + 1]) uf_unite(i, j + 1);
    } else {
        // vertical boundary: col x = 32b+31 vs x+1
        r -= 31*1024;
        int b = r >> 10, y = r & 1023;
        int x = 32*b + 31;
        int i = base + (y << 10) + x;
        if (!g_code[i]) return;
        if (g_code[i + 1]) uf_unite(i, i + 1);
        if ((y & 31) != 0  && g_code[i + 1 - IW]) uf_unite(i, i + 1 - IW);
        if ((y & 31) != 31 && g_code[i + 1 + IW]) uf_unite(i, i + 1 + IW);
    }
}

// =================================================================
// Flatten: compress all on-pixels to final root + flag strong roots
// =================================================================
__global__ __launch_bounds__(256) void k_flatten() {
    int t = blockIdx.x * blockDim.x + threadIdx.x;
    if (t >= NP/4) return;
    uchar4 c = reinterpret_cast<const uchar4*>(g_code)[t];
    int i0 = t * 4;
    if (c.x) { int r = uf_rep(i0);   g_lab[i0]   = r; if (c.x == 2) g_flag[r] = 1; }
    if (c.y) { int r = uf_rep(i0+1); g_lab[i0+1] = r; if (c.y == 2) g_flag[r] = 1; }
    if (c.z) { int r = uf_rep(i0+2); g_lab[i0+2] = r; if (c.z == 2) g_flag[r] = 1; }
    if (c.w) { int r = uf_rep(i0+3); g_lab[i0+3] = r; if (c.w == 2) g_flag[r] = 1; }
}

// =================================================================
// Final: single-hop lookup, vectorized
// =================================================================
__global__ __launch_bounds__(256) void k_final(float* __restrict__ out_hyst) {
    int t = blockIdx.x * blockDim.x + threadIdx.x;
    if (t >= NP/4) return;
    uchar4 c = reinterpret_cast<const uchar4*>(g_code)[t];
    int i0 = t * 4;
    float4 v = make_float4(0.f, 0.f, 0.f, 0.f);
    if (c.x && g_flag[g_lab[i0  ]]) v.x = 1.f;
    if (c.y && g_flag[g_lab[i0+1]]) v.y = 1.f;
    if (c.z && g_flag[g_lab[i0+2]]) v.z = 1.f;
    if (c.w && g_flag[g_lab[i0+3]]) v.w = 1.f;
    reinterpret_cast<float4*>(out_hyst)[t] = v;
}

// =================================================================
extern "C" void kernel_launch(void* const* d_in, const int* in_sizes, int n_in,
                              void* d_out, int out_size) {
    const float* img = (const float*)d_in[0];
    float* out = (float*)d_out;   // [0,NP): magnitude, [NP,2NP): hysteresis

    dim3 fgrid(IW/32, IH/32, NIMG);
    k_front<<<fgrid, 256>>>(img, out);

    const int T = 256;
    k_boundary<<<(NIMG*PER_IMG + T - 1)/T, T>>>();
    k_flatten<<<(NP/4 + T - 1)/T, T>>>();
    k_final<<<(NP/4 + T - 1)/T, T>>>(out + NP);
}